// round 1
// baseline (speedup 1.0000x reference)
#include <cuda_runtime.h>
#include <math.h>

#define TD 1024     // hidden dim D
#define TE 64       // experts E
#define BM 64       // tokens per block
#define BK 32       // k-chunk
#define XS_STRIDE 66
#define WS_STRIDE 66
#define CS_STRIDE 65

__device__ __forceinline__ unsigned long long pack2(float lo, float hi) {
    unsigned long long r;
    asm("mov.b64 %0, {%1, %2};" : "=l"(r) : "f"(lo), "f"(hi));
    return r;
}
__device__ __forceinline__ void unpack2(unsigned long long v, float& lo, float& hi) {
    asm("mov.b64 {%0, %1}, %2;" : "=f"(lo), "=f"(hi) : "l"(v));
}
__device__ __forceinline__ void ffma2(unsigned long long& d, unsigned long long a, unsigned long long b) {
    asm("fma.rn.f32x2 %0, %1, %2, %0;" : "+l"(d) : "l"(a), "l"(b));
}

__global__ void __launch_bounds__(128) gate_kernel(
    const float* __restrict__ x,      // [T, D]
    const float* __restrict__ gw,     // [E, D]
    const float* __restrict__ nw,     // [E]
    const float* __restrict__ noise,  // [T, E]
    float* __restrict__ out,          // [T*E weights][T*2 idx-as-float]
    int T, int write_idx)
{
    __shared__ __align__(16) float Xs[BK * XS_STRIDE];
    __shared__ __align__(16) float Ws[BK * WS_STRIDE];
    __shared__ __align__(16) float Cs[BM * CS_STRIDE];
    __shared__ float nws[TE];

    const int tid = threadIdx.x;
    const int tx = tid & 15;   // expert group: experts tx*4 .. tx*4+3
    const int ty = tid >> 4;   // token group: tokens ty*8 .. ty*8+7
    const long long t0 = (long long)blockIdx.x * BM;

    if (tid < TE) nws[tid] = nw[tid];

    // 16 packed accumulators: acc[i][j] = (token ty*8+2i, token ty*8+2i+1) x expert tx*4+j
    unsigned long long acc[4][4];
    #pragma unroll
    for (int i = 0; i < 4; i++)
        #pragma unroll
        for (int j = 0; j < 4; j++) acc[i][j] = 0ull;

    // register prefetch of chunk 0
    float4 xr[4], wr[4];
    #pragma unroll
    for (int i = 0; i < 4; i++) {
        int idx = i * 128 + tid;          // 0..511
        int row = idx >> 3;               // 0..63
        int c4  = idx & 7;                // float4 index along k
        xr[i] = *reinterpret_cast<const float4*>(x  + (t0 + row) * TD + c4 * 4);
        wr[i] = *reinterpret_cast<const float4*>(gw + (long long)row * TD + c4 * 4);
    }

    for (int k0 = 0; k0 < TD; k0 += BK) {
        __syncthreads();   // previous chunk's compute done before smem overwrite
        #pragma unroll
        for (int i = 0; i < 4; i++) {
            int idx = i * 128 + tid;
            int row = idx >> 3;
            int c4  = idx & 7;
            Xs[(c4*4+0)*XS_STRIDE + row] = xr[i].x;
            Xs[(c4*4+1)*XS_STRIDE + row] = xr[i].y;
            Xs[(c4*4+2)*XS_STRIDE + row] = xr[i].z;
            Xs[(c4*4+3)*XS_STRIDE + row] = xr[i].w;
            Ws[(c4*4+0)*WS_STRIDE + row] = wr[i].x;
            Ws[(c4*4+1)*WS_STRIDE + row] = wr[i].y;
            Ws[(c4*4+2)*WS_STRIDE + row] = wr[i].z;
            Ws[(c4*4+3)*WS_STRIDE + row] = wr[i].w;
        }
        __syncthreads();
        if (k0 + BK < TD) {   // prefetch next chunk (overlaps compute below)
            #pragma unroll
            for (int i = 0; i < 4; i++) {
                int idx = i * 128 + tid;
                int row = idx >> 3;
                int c4  = idx & 7;
                xr[i] = *reinterpret_cast<const float4*>(x  + (t0 + row) * TD + (k0 + BK) + c4 * 4);
                wr[i] = *reinterpret_cast<const float4*>(gw + (long long)row * TD + (k0 + BK) + c4 * 4);
            }
        }
        #pragma unroll
        for (int k = 0; k < BK; k++) {
            unsigned long long a2[4];
            const unsigned long long* xp =
                reinterpret_cast<const unsigned long long*>(Xs + k * XS_STRIDE + ty * 8);
            #pragma unroll
            for (int i = 0; i < 4; i++) a2[i] = xp[i];
            unsigned long long b2[4];
            #pragma unroll
            for (int j = 0; j < 4; j++) {
                float b = Ws[k * WS_STRIDE + tx * 4 + j];
                b2[j] = pack2(b, b);
            }
            #pragma unroll
            for (int i = 0; i < 4; i++)
                #pragma unroll
                for (int j = 0; j < 4; j++)
                    ffma2(acc[i][j], a2[i], b2[j]);
        }
    }

    __syncthreads();
    // epilogue part 1: logits + noise*nw -> Cs
    #pragma unroll
    for (int i = 0; i < 4; i++) {
        int m = ty * 8 + 2 * i;
        float4 n0 = *reinterpret_cast<const float4*>(noise + (t0 + m)     * TE + tx * 4);
        float4 n1 = *reinterpret_cast<const float4*>(noise + (t0 + m + 1) * TE + tx * 4);
        float na[4] = {n0.x, n0.y, n0.z, n0.w};
        float nb[4] = {n1.x, n1.y, n1.z, n1.w};
        #pragma unroll
        for (int j = 0; j < 4; j++) {
            int e = tx * 4 + j;
            float lo, hi;
            unpack2(acc[i][j], lo, hi);
            float s = nws[e];
            Cs[m       * CS_STRIDE + e] = lo + na[j] * s;
            Cs[(m + 1) * CS_STRIDE + e] = hi + nb[j] * s;
        }
    }
    __syncthreads();

    // epilogue part 2: coalesced zero-fill of this block's weight rows
    {
        float4 z = make_float4(0.f, 0.f, 0.f, 0.f);
        float4* outw4 = reinterpret_cast<float4*>(out + t0 * TE);
        #pragma unroll
        for (int i = 0; i < 8; i++) outw4[i * 128 + tid] = z;  // 1024 float4 = 64*64 floats
    }
    __syncthreads();

    // epilogue part 3: per-token top-2 + softmax scatter
    if (tid < BM) {
        const float* row = Cs + tid * CS_STRIDE;
        float v1 = -3.402823466e38f, v2 = -3.402823466e38f;
        int i1 = 0, i2 = 0;
        #pragma unroll
        for (int e = 0; e < TE; e++) {
            float v = row[e];
            if (v > v1) { v2 = v1; i2 = i1; v1 = v; i1 = e; }
            else if (v > v2) { v2 = v; i2 = e; }
        }
        float e2 = expf(v2 - v1);
        float s  = 1.0f + e2;
        float w1 = 1.0f / s;
        float w2 = e2 / s;
        long long t = t0 + tid;
        out[t * TE + i1] = w1;
        out[t * TE + i2] = w2;
        if (write_idx) {
            float* oi = out + (long long)T * TE;
            oi[t * 2 + 0] = (float)i1;
            oi[t * 2 + 1] = (float)i2;
        }
    }
}

extern "C" void kernel_launch(void* const* d_in, const int* in_sizes, int n_in,
                              void* d_out, int out_size) {
    const float* x     = (const float*)d_in[0];
    const float* gw    = (const float*)d_in[1];
    const float* nw    = (const float*)d_in[2];
    const float* noise = (const float*)d_in[3];
    float* out = (float*)d_out;

    int T = in_sizes[0] / TD;                    // 16384 tokens
    int write_idx = (out_size >= T * TE + T * 2) ? 1 : 0;

    gate_kernel<<<T / BM, 128>>>(x, gw, nw, noise, out, T, write_idx);
}